// round 7
// baseline (speedup 1.0000x reference)
#include <cuda_runtime.h>
#include <cuda_bf16.h>

#define NN 30000
#define NE 240000
#define D1 512
#define D2 128
#define H 2
#define C1 256
#define C2 64
#define NCLS 20
#define EPS 1e-5f
#define NEG 0.2f

// ---------------- scratch ----------------
__device__ float g_xlr1[(size_t)NN * 2 * D1];
__device__ float g_acc1[(size_t)NN * D1];
__device__ float g_xlr2[(size_t)NN * 2 * D2];
__device__ float g_acc2[(size_t)NN * D2];
__device__ int g_deg[NN];
__device__ int g_off[NN + 1];
__device__ int g_cursor[NN];
__device__ int g_srcs[NE];
__device__ float g_eas[NE];

// ---------------- CSR build ----------------
__global__ void zero_deg_k(int* deg) {
    int i = blockIdx.x * blockDim.x + threadIdx.x;
    if (i < NN) deg[i] = 0;
}
__global__ void hist_k(const int* __restrict__ dst, int* __restrict__ deg) {
    int e = blockIdx.x * blockDim.x + threadIdx.x;
    if (e < NE) atomicAdd(&deg[dst[e]], 1);
}
__global__ __launch_bounds__(1024) void scan_k(const int* __restrict__ deg,
                                               int* __restrict__ off, int* __restrict__ cursor) {
    __shared__ int partial[1024];
    int t = threadIdx.x;
    const int CH = (NN + 1023) / 1024;
    int base = t * CH;
    int s = 0;
    for (int i = 0; i < CH; i++) {
        int idx = base + i;
        if (idx < NN) s += deg[idx];
    }
    partial[t] = s;
    __syncthreads();
    for (int o = 1; o < 1024; o <<= 1) {
        int v = (t >= o) ? partial[t - o] : 0;
        __syncthreads();
        partial[t] += v;
        __syncthreads();
    }
    int run = (t == 0) ? 0 : partial[t - 1];
    for (int i = 0; i < CH; i++) {
        int idx = base + i;
        if (idx < NN) {
            off[idx] = run;
            cursor[idx] = run;
            run += deg[idx];
        }
    }
    if (t == 1023) off[NN] = partial[1023];
}
__global__ void scatter_k(const int* __restrict__ src, const int* __restrict__ dst,
                          const float* __restrict__ eattr, int* __restrict__ cursor,
                          int* __restrict__ srcs, float* __restrict__ eas) {
    int e = blockIdx.x * blockDim.x + threadIdx.x;
    if (e < NE) {
        int pos = atomicAdd(&cursor[dst[e]], 1);
        srcs[pos] = src[e];
        eas[pos] = eattr[e];
    }
}

// ---------------- BF16 split helpers ----------------
__device__ __forceinline__ void split2_bf16(float f0, float f1, unsigned& hi, unsigned& lo) {
    __nv_bfloat162 h = __floats2bfloat162_rn(f0, f1);
    float r0 = f0 - __bfloat162float(h.x);
    float r1 = f1 - __bfloat162float(h.y);
    __nv_bfloat162 l = __floats2bfloat162_rn(r0, r1);
    hi = *(unsigned*)&h;
    lo = *(unsigned*)&l;
}
__device__ __forceinline__ void mma_bf16(float* c, const unsigned* a, const unsigned* b) {
    asm volatile(
        "mma.sync.aligned.m16n8k16.row.col.f32.bf16.bf16.f32 "
        "{%0,%1,%2,%3}, {%4,%5,%6,%7}, {%8,%9}, {%0,%1,%2,%3};\n"
        : "+f"(c[0]), "+f"(c[1]), "+f"(c[2]), "+f"(c[3])
        : "r"(a[0]), "r"(a[1]), "r"(a[2]), "r"(a[3]), "r"(b[0]), "r"(b[1]));
}

// ---------------- dual-B TC GEMM, 3xBF16, 128x128 block, 64x32 warp tile, 2-stage ----------------
// C[M, 2*Nhalf]: cols [0,Nhalf) = A@B0^T+bias0 ; [Nhalf,2Nhalf) = A@B1^T+bias1
__global__ __launch_bounds__(256, 1) void gemm_bf3_k(
    const float* __restrict__ A,
    const float* __restrict__ B0, const float* __restrict__ B1,
    const float* __restrict__ bias0, const float* __restrict__ bias1,
    float* __restrict__ C, int M, int Nhalf, int K) {
    const int N = 2 * Nhalf;
    __shared__ unsigned AsH[2][128][12], AsL[2][128][12];
    __shared__ unsigned BsH[2][128][12], BsL[2][128][12];

    const int tid = threadIdx.x;
    const int lane = tid & 31;
    const int warp = tid >> 5;
    const int wm = warp >> 2;       // 0..1 -> 64-row slab
    const int wn = warp & 3;        // 0..3 -> 32-col slab
    const int groupID = lane >> 2;  // 0..7
    const int tg = lane & 3;        // 0..3

    const int bm = blockIdx.y * 128;
    const int bn = blockIdx.x * 128;

    // loader coords: rows r and r+64 for both A and B, 4 k-elements each
    const int lr = tid >> 2;                // 0..63
    const int ak4 = (tid & 3) * 4;
    const int pc = (tid & 3) * 2;
    int agr0 = bm + lr;      if (agr0 >= M) agr0 = M - 1;
    int agr1 = bm + lr + 64; if (agr1 >= M) agr1 = M - 1;
    const int gn0 = bn + lr, gn1 = bn + lr + 64;
    const float* Bp0 = (gn0 < Nhalf) ? B0 : B1;
    const float* Bp1 = (gn1 < Nhalf) ? B0 : B1;
    const int bc0 = (gn0 < Nhalf) ? gn0 : gn0 - Nhalf;
    const int bc1 = (gn1 < Nhalf) ? gn1 : gn1 - Nhalf;

    float4 a0 = *(const float4*)&A[(size_t)agr0 * K + ak4];
    float4 a1 = *(const float4*)&A[(size_t)agr1 * K + ak4];
    float4 b0 = *(const float4*)&Bp0[(size_t)bc0 * K + ak4];
    float4 b1 = *(const float4*)&Bp1[(size_t)bc1 * K + ak4];

    // store tile 0 into buffer 0
    {
        unsigned hi, lo;
        split2_bf16(a0.x, a0.y, hi, lo); AsH[0][lr][pc] = hi; AsL[0][lr][pc] = lo;
        split2_bf16(a0.z, a0.w, hi, lo); AsH[0][lr][pc + 1] = hi; AsL[0][lr][pc + 1] = lo;
        split2_bf16(a1.x, a1.y, hi, lo); AsH[0][lr + 64][pc] = hi; AsL[0][lr + 64][pc] = lo;
        split2_bf16(a1.z, a1.w, hi, lo); AsH[0][lr + 64][pc + 1] = hi; AsL[0][lr + 64][pc + 1] = lo;
        split2_bf16(b0.x, b0.y, hi, lo); BsH[0][lr][pc] = hi; BsL[0][lr][pc] = lo;
        split2_bf16(b0.z, b0.w, hi, lo); BsH[0][lr][pc + 1] = hi; BsL[0][lr][pc + 1] = lo;
        split2_bf16(b1.x, b1.y, hi, lo); BsH[0][lr + 64][pc] = hi; BsL[0][lr + 64][pc] = lo;
        split2_bf16(b1.z, b1.w, hi, lo); BsH[0][lr + 64][pc + 1] = hi; BsL[0][lr + 64][pc + 1] = lo;
    }

    float acc[4][4][4] = {};
    int buf = 0;

    for (int k0 = 0; k0 < K; k0 += 16) {
        __syncthreads();
        bool more = (k0 + 16) < K;
        if (more) {
            a0 = *(const float4*)&A[(size_t)agr0 * K + k0 + 16 + ak4];
            a1 = *(const float4*)&A[(size_t)agr1 * K + k0 + 16 + ak4];
            b0 = *(const float4*)&Bp0[(size_t)bc0 * K + k0 + 16 + ak4];
            b1 = *(const float4*)&Bp1[(size_t)bc1 * K + k0 + 16 + ak4];
        }

        // B fragments for this warp's 32 columns
        unsigned bh[4][2], bl[4][2];
#pragma unroll
        for (int nt = 0; nt < 4; nt++) {
            int n = wn * 32 + nt * 8 + groupID;
            bh[nt][0] = BsH[buf][n][tg];     bl[nt][0] = BsL[buf][n][tg];
            bh[nt][1] = BsH[buf][n][tg + 4]; bl[nt][1] = BsL[buf][n][tg + 4];
        }
#pragma unroll
        for (int mt = 0; mt < 4; mt++) {
            int r = wm * 64 + mt * 16 + groupID;
            unsigned ah[4], al[4];
            ah[0] = AsH[buf][r][tg];         al[0] = AsL[buf][r][tg];
            ah[1] = AsH[buf][r + 8][tg];     al[1] = AsL[buf][r + 8][tg];
            ah[2] = AsH[buf][r][tg + 4];     al[2] = AsL[buf][r][tg + 4];
            ah[3] = AsH[buf][r + 8][tg + 4]; al[3] = AsL[buf][r + 8][tg + 4];
#pragma unroll
            for (int nt = 0; nt < 4; nt++) {
                mma_bf16(acc[mt][nt], ah, bh[nt]);
                mma_bf16(acc[mt][nt], al, bh[nt]);
                mma_bf16(acc[mt][nt], ah, bl[nt]);
            }
        }

        if (more) {
            int nb = buf ^ 1;
            unsigned hi, lo;
            split2_bf16(a0.x, a0.y, hi, lo); AsH[nb][lr][pc] = hi; AsL[nb][lr][pc] = lo;
            split2_bf16(a0.z, a0.w, hi, lo); AsH[nb][lr][pc + 1] = hi; AsL[nb][lr][pc + 1] = lo;
            split2_bf16(a1.x, a1.y, hi, lo); AsH[nb][lr + 64][pc] = hi; AsL[nb][lr + 64][pc] = lo;
            split2_bf16(a1.z, a1.w, hi, lo); AsH[nb][lr + 64][pc + 1] = hi; AsL[nb][lr + 64][pc + 1] = lo;
            split2_bf16(b0.x, b0.y, hi, lo); BsH[nb][lr][pc] = hi; BsL[nb][lr][pc] = lo;
            split2_bf16(b0.z, b0.w, hi, lo); BsH[nb][lr][pc + 1] = hi; BsL[nb][lr][pc + 1] = lo;
            split2_bf16(b1.x, b1.y, hi, lo); BsH[nb][lr + 64][pc] = hi; BsL[nb][lr + 64][pc] = lo;
            split2_bf16(b1.z, b1.w, hi, lo); BsH[nb][lr + 64][pc + 1] = hi; BsL[nb][lr + 64][pc + 1] = lo;
        }
        buf ^= 1;
    }

#pragma unroll
    for (int mt = 0; mt < 4; mt++) {
        int row0 = bm + wm * 64 + mt * 16 + groupID;
#pragma unroll
        for (int nt = 0; nt < 4; nt++) {
            int col0 = bn + wn * 32 + nt * 8 + tg * 2;
            float bb0 = (col0 < Nhalf) ? bias0[col0] : bias1[col0 - Nhalf];
            float bb1 = (col0 + 1 < Nhalf) ? bias0[col0 + 1] : bias1[col0 + 1 - Nhalf];
            if (row0 < M) {
                C[(size_t)row0 * N + col0] = acc[mt][nt][0] + bb0;
                C[(size_t)row0 * N + col0 + 1] = acc[mt][nt][1] + bb1;
            }
            if (row0 + 8 < M) {
                C[(size_t)(row0 + 8) * N + col0] = acc[mt][nt][2] + bb0;
                C[(size_t)(row0 + 8) * N + col0 + 1] = acc[mt][nt][3] + bb1;
            }
        }
    }
}

// ---------------- CSR edge pass, layer 1 (C=256): warp per (dst, head) ----------------
__global__ __launch_bounds__(256) void gat_edge1_k(
    const int* __restrict__ srcs, const float* __restrict__ eas,
    const int* __restrict__ off,
    const float* __restrict__ xlr, const float* __restrict__ We,
    const float* __restrict__ att, float* __restrict__ outv) {
    int gw = (blockIdx.x * 256 + threadIdx.x) >> 5;
    int lane = threadIdx.x & 31;
    if (gw >= NN * H) return;
    int h = gw & 1;
    int d = gw >> 1;
    const int STR = 2 * D1;
    const int c0 = lane * 4, c1 = 128 + lane * 4;

    const float* xrd = xlr + (size_t)d * STR + D1 + h * C1;
    float4 xr_a = *(const float4*)&xrd[c0];
    float4 xr_b = *(const float4*)&xrd[c1];
    const float* Weh = We + h * C1;
    float4 w_a = *(const float4*)&Weh[c0];
    float4 w_b = *(const float4*)&Weh[c1];
    const float* ath = att + h * C1;
    float4 t_a = *(const float4*)&ath[c0];
    float4 t_b = *(const float4*)&ath[c1];

    float4 acc_a = {0, 0, 0, 0}, acc_b = {0, 0, 0, 0};
    float denom = 0.f, easum = 0.f;
    int i0 = off[d], i1 = off[d + 1];

    for (int i = i0; i <= i1; i++) {
        int s;
        float ea;
        if (i < i1) {
            s = srcs[i];
            ea = eas[i];
            easum += ea;
        } else {
            s = d;
            ea = easum / fmaxf((float)(i1 - i0), 1.f);
        }
        const float* xls = xlr + (size_t)s * STR + h * C1;
        float4 a_a = *(const float4*)&xls[c0];
        float4 a_b = *(const float4*)&xls[c1];
        float v, lg = 0.f;
        v = a_a.x + xr_a.x + ea * w_a.x; v = v > 0.f ? v : NEG * v; lg += v * t_a.x;
        v = a_a.y + xr_a.y + ea * w_a.y; v = v > 0.f ? v : NEG * v; lg += v * t_a.y;
        v = a_a.z + xr_a.z + ea * w_a.z; v = v > 0.f ? v : NEG * v; lg += v * t_a.z;
        v = a_a.w + xr_a.w + ea * w_a.w; v = v > 0.f ? v : NEG * v; lg += v * t_a.w;
        v = a_b.x + xr_b.x + ea * w_b.x; v = v > 0.f ? v : NEG * v; lg += v * t_b.x;
        v = a_b.y + xr_b.y + ea * w_b.y; v = v > 0.f ? v : NEG * v; lg += v * t_b.y;
        v = a_b.z + xr_b.z + ea * w_b.z; v = v > 0.f ? v : NEG * v; lg += v * t_b.z;
        v = a_b.w + xr_b.w + ea * w_b.w; v = v > 0.f ? v : NEG * v; lg += v * t_b.w;
#pragma unroll
        for (int o = 16; o > 0; o >>= 1) lg += __shfl_xor_sync(0xffffffffu, lg, o);
        float p = __expf(lg);
        denom += p;
        acc_a.x += p * a_a.x; acc_a.y += p * a_a.y; acc_a.z += p * a_a.z; acc_a.w += p * a_a.w;
        acc_b.x += p * a_b.x; acc_b.y += p * a_b.y; acc_b.z += p * a_b.z; acc_b.w += p * a_b.w;
    }
    float inv = 1.f / denom;
    float* od = outv + (size_t)d * D1 + h * C1;
    float4 o_a = {acc_a.x * inv, acc_a.y * inv, acc_a.z * inv, acc_a.w * inv};
    float4 o_b = {acc_b.x * inv, acc_b.y * inv, acc_b.z * inv, acc_b.w * inv};
    *(float4*)&od[c0] = o_a;
    *(float4*)&od[c1] = o_b;
}

// ---------------- CSR edge pass, layer 2 (C=64): warp per dst ----------------
__global__ __launch_bounds__(256) void gat_edge2_k(
    const int* __restrict__ srcs, const float* __restrict__ eas,
    const int* __restrict__ off,
    const float* __restrict__ xlr, const float* __restrict__ We,
    const float* __restrict__ att, float* __restrict__ outv) {
    int gw = (blockIdx.x * 256 + threadIdx.x) >> 5;
    int lane = threadIdx.x & 31;
    if (gw >= NN) return;
    int d = gw;
    const int STR = 2 * D2;
    int h = lane >> 4;
    int cl = (lane & 15) * 4;
    int gc = h * C2 + cl;

    const float* xrd = xlr + (size_t)d * STR + D2;
    float4 xr_v = *(const float4*)&xrd[gc];
    float4 w_v = *(const float4*)&We[gc];
    float4 t_v = *(const float4*)&att[gc];

    float4 acc = {0, 0, 0, 0};
    float denom = 0.f, easum = 0.f;
    int i0 = off[d], i1 = off[d + 1];

    for (int i = i0; i <= i1; i++) {
        int s;
        float ea;
        if (i < i1) {
            s = srcs[i];
            ea = eas[i];
            easum += ea;
        } else {
            s = d;
            ea = easum / fmaxf((float)(i1 - i0), 1.f);
        }
        const float* xls = xlr + (size_t)s * STR;
        float4 a = *(const float4*)&xls[gc];
        float v, lg = 0.f;
        v = a.x + xr_v.x + ea * w_v.x; v = v > 0.f ? v : NEG * v; lg += v * t_v.x;
        v = a.y + xr_v.y + ea * w_v.y; v = v > 0.f ? v : NEG * v; lg += v * t_v.y;
        v = a.z + xr_v.z + ea * w_v.z; v = v > 0.f ? v : NEG * v; lg += v * t_v.z;
        v = a.w + xr_v.w + ea * w_v.w; v = v > 0.f ? v : NEG * v; lg += v * t_v.w;
#pragma unroll
        for (int o = 8; o > 0; o >>= 1) lg += __shfl_xor_sync(0xffffffffu, lg, o);
        float p = __expf(lg);
        denom += p;
        acc.x += p * a.x; acc.y += p * a.y; acc.z += p * a.z; acc.w += p * a.w;
    }
    float inv = 1.f / denom;
    float* od = outv + (size_t)d * D2 + gc;
    float4 o = {acc.x * inv, acc.y * inv, acc.z * inv, acc.w * inv};
    *(float4*)&od[0] = o;
}

// ---------------- bias + (silu) + rmsnorm ----------------
__global__ void postact_rms_k(const float* __restrict__ acc, const float* __restrict__ bias,
                              const float* __restrict__ w, float* __restrict__ out,
                              int D, int do_silu) {
    int n = blockIdx.x;
    float vals[2];
    float ss = 0.f;
    int nv = 0;
    for (int j = threadIdx.x; j < D; j += blockDim.x) {
        float v = acc[(size_t)n * D + j] + bias[j];
        if (do_silu) v = v / (1.f + __expf(-v));
        vals[nv++] = v;
        ss += v * v;
    }
    __shared__ float red[32];
    int lane = threadIdx.x & 31, wid = threadIdx.x >> 5;
#pragma unroll
    for (int o = 16; o > 0; o >>= 1) ss += __shfl_down_sync(0xffffffffu, ss, o);
    if (lane == 0) red[wid] = ss;
    __syncthreads();
    if (wid == 0) {
        float s2 = (lane < (blockDim.x >> 5)) ? red[lane] : 0.f;
#pragma unroll
        for (int o = 16; o > 0; o >>= 1) s2 += __shfl_down_sync(0xffffffffu, s2, o);
        if (lane == 0) red[0] = s2;
    }
    __syncthreads();
    float inv = rsqrtf(red[0] / (float)D + EPS);
    nv = 0;
    for (int j = threadIdx.x; j < D; j += blockDim.x)
        out[(size_t)n * D + j] = vals[nv++] * inv * w[j];
}

// ---------------- classifier ----------------
__global__ void out_gemm_k(const float* __restrict__ h, const float* __restrict__ W,
                           float* __restrict__ out, int N, int K, int Cn) {
    extern __shared__ float Ws[];
    for (int i = threadIdx.x; i < Cn * K; i += blockDim.x) Ws[i] = W[i];
    __syncthreads();
    int idx = blockIdx.x * blockDim.x + threadIdx.x;
    if (idx >= N * Cn) return;
    int n = idx / Cn, c = idx % Cn;
    const float* hr = h + (size_t)n * K;
    const float* wr = Ws + c * K;
    float s = 0.f;
#pragma unroll 8
    for (int k = 0; k < K; k++) s += hr[k] * wr[k];
    out[idx] = s;
}

// ---------------- launch ----------------
static void* sym(const void* s) {
    void* p = nullptr;
    cudaGetSymbolAddress(&p, s);
    return p;
}

extern "C" void kernel_launch(void* const* d_in, const int* in_sizes, int n_in,
                              void* d_out, int out_size) {
    const float* x     = (const float*)d_in[0];
    const int*   ei    = (const int*)d_in[1];
    const float* eattr = (const float*)d_in[2];
    const float* Wl1   = (const float*)d_in[3];
    const float* bl1   = (const float*)d_in[4];
    const float* Wr1   = (const float*)d_in[5];
    const float* br1   = (const float*)d_in[6];
    const float* We1   = (const float*)d_in[7];
    const float* att1  = (const float*)d_in[8];
    const float* bias1 = (const float*)d_in[9];
    const float* Wl2   = (const float*)d_in[10];
    const float* bl2   = (const float*)d_in[11];
    const float* Wr2   = (const float*)d_in[12];
    const float* br2   = (const float*)d_in[13];
    const float* We2   = (const float*)d_in[14];
    const float* att2  = (const float*)d_in[15];
    const float* bias2 = (const float*)d_in[16];
    const float* w_ln1 = (const float*)d_in[17];
    const float* w_ln3 = (const float*)d_in[18];
    const float* W_out = (const float*)d_in[19];
    float* out = (float*)d_out;

    const int* srcp = ei;
    const int* dstp = ei + NE;

    float* xlr1 = (float*)sym(g_xlr1);
    float* acc1 = (float*)sym(g_acc1);
    float* xlr2 = (float*)sym(g_xlr2);
    float* acc2 = (float*)sym(g_acc2);
    int* deg    = (int*)sym(g_deg);
    int* off    = (int*)sym(g_off);
    int* cursor = (int*)sym(g_cursor);
    int* srcs   = (int*)sym(g_srcs);
    float* eas  = (float*)sym(g_eas);

    // 0-2: CSR histogram + scan
    zero_deg_k<<<(NN + 255) / 256, 256>>>(deg);
    hist_k<<<(NE + 255) / 256, 256>>>(dstp, deg);
    scan_k<<<1, 1024>>>(deg, off, cursor);

    // 3: layer 1 fused transforms (profiler capture slot): N=1024 -> 8 col tiles
    dim3 g1(2 * D1 / 128, (NN + 127) / 128);
    gemm_bf3_k<<<g1, 256>>>(x, Wl1, Wr1, bl1, br1, xlr1, NN, D1, D2);

    // 4: permute edges into CSR order
    scatter_k<<<(NE + 255) / 256, 256>>>(srcp, dstp, eattr, cursor, srcs, eas);

    // 5: CSR edge pass layer 1
    gat_edge1_k<<<(NN * H * 32 + 255) / 256, 256>>>(srcs, eas, off, xlr1, We1, att1, acc1);

    // 6: silu + rmsnorm
    postact_rms_k<<<NN, 256>>>(acc1, bias1, w_ln1, acc1, D1, 1);

    // 7: layer 2 fused transforms: N=256 -> 2 col tiles
    dim3 g2(2 * D2 / 128, (NN + 127) / 128);
    gemm_bf3_k<<<g2, 256>>>(acc1, Wl2, Wr2, bl2, br2, xlr2, NN, D2, D1);

    // 8: CSR edge pass layer 2
    gat_edge2_k<<<(NN * 32 + 255) / 256, 256>>>(srcs, eas, off, xlr2, We2, att2, acc2);

    // 9: rmsnorm
    postact_rms_k<<<NN, 256>>>(acc2, bias2, w_ln3, acc2, D2, 0);

    // 10: classifier
    int ntot = NN * NCLS;
    out_gemm_k<<<(ntot + 255) / 256, 256, NCLS * D2 * sizeof(float)>>>(acc2, W_out, out, NN, D2, NCLS);
}

// round 8
// speedup vs baseline: 1.0061x; 1.0061x over previous
#include <cuda_runtime.h>
#include <cuda_bf16.h>

#define NN 30000
#define NE 240000
#define D1 512
#define D2 128
#define H 2
#define C1 256
#define C2 64
#define NCLS 20
#define EPS 1e-5f
#define NEG 0.2f

// ---------------- scratch ----------------
__device__ float g_xlr1[(size_t)NN * 2 * D1];
__device__ float g_acc1[(size_t)NN * D1];
__device__ float g_xlr2[(size_t)NN * 2 * D2];
__device__ float g_acc2[(size_t)NN * D2];
__device__ int g_deg[NN];
__device__ int g_off[NN + 1];
__device__ int g_cursor[NN];
__device__ int g_srcs[NE];
__device__ float g_eas[NE];

// ---------------- CSR build ----------------
__global__ void zero_deg_k(int* deg) {
    int i = blockIdx.x * blockDim.x + threadIdx.x;
    if (i < NN) deg[i] = 0;
}
__global__ void hist_k(const int* __restrict__ dst, int* __restrict__ deg) {
    int e = blockIdx.x * blockDim.x + threadIdx.x;
    if (e < NE) atomicAdd(&deg[dst[e]], 1);
}
__global__ __launch_bounds__(1024) void scan_k(const int* __restrict__ deg,
                                               int* __restrict__ off, int* __restrict__ cursor) {
    __shared__ int partial[1024];
    int t = threadIdx.x;
    const int CH = (NN + 1023) / 1024;
    int base = t * CH;
    int s = 0;
    for (int i = 0; i < CH; i++) {
        int idx = base + i;
        if (idx < NN) s += deg[idx];
    }
    partial[t] = s;
    __syncthreads();
    for (int o = 1; o < 1024; o <<= 1) {
        int v = (t >= o) ? partial[t - o] : 0;
        __syncthreads();
        partial[t] += v;
        __syncthreads();
    }
    int run = (t == 0) ? 0 : partial[t - 1];
    for (int i = 0; i < CH; i++) {
        int idx = base + i;
        if (idx < NN) {
            off[idx] = run;
            cursor[idx] = run;
            run += deg[idx];
        }
    }
    if (t == 1023) off[NN] = partial[1023];
}
__global__ void scatter_k(const int* __restrict__ src, const int* __restrict__ dst,
                          const float* __restrict__ eattr, int* __restrict__ cursor,
                          int* __restrict__ srcs, float* __restrict__ eas) {
    int e = blockIdx.x * blockDim.x + threadIdx.x;
    if (e < NE) {
        int pos = atomicAdd(&cursor[dst[e]], 1);
        srcs[pos] = src[e];
        eas[pos] = eattr[e];
    }
}

// ---------------- BF16 split helpers ----------------
__device__ __forceinline__ void split2_bf16(float f0, float f1, unsigned& hi, unsigned& lo) {
    __nv_bfloat162 h = __floats2bfloat162_rn(f0, f1);
    float r0 = f0 - __bfloat162float(h.x);
    float r1 = f1 - __bfloat162float(h.y);
    __nv_bfloat162 l = __floats2bfloat162_rn(r0, r1);
    hi = *(unsigned*)&h;
    lo = *(unsigned*)&l;
}
__device__ __forceinline__ void mma_bf16(float* c, const unsigned* a, const unsigned* b) {
    asm volatile(
        "mma.sync.aligned.m16n8k16.row.col.f32.bf16.bf16.f32 "
        "{%0,%1,%2,%3}, {%4,%5,%6,%7}, {%8,%9}, {%0,%1,%2,%3};\n"
        : "+f"(c[0]), "+f"(c[1]), "+f"(c[2]), "+f"(c[3])
        : "r"(a[0]), "r"(a[1]), "r"(a[2]), "r"(a[3]), "r"(b[0]), "r"(b[1]));
}

// ---------------- dual-B TC GEMM, 3xBF16, 128x64 block, 32x32 warp tile, DOUBLE BUFFER ----------------
__global__ __launch_bounds__(256) void gemm_bf3_k(
    const float* __restrict__ A,
    const float* __restrict__ B0, const float* __restrict__ B1,
    const float* __restrict__ bias0, const float* __restrict__ bias1,
    float* __restrict__ C, int M, int Nhalf, int K) {
    const int N = 2 * Nhalf;
    __shared__ unsigned AsH[2][128][12], AsL[2][128][12];
    __shared__ unsigned BsH[2][64][12], BsL[2][64][12];

    const int tid = threadIdx.x;
    const int lane = tid & 31;
    const int warp = tid >> 5;
    const int wm = warp >> 1;       // 0..3
    const int wn = warp & 1;        // 0..1
    const int groupID = lane >> 2;  // 0..7
    const int tg = lane & 3;        // 0..3

    const int bm = blockIdx.y * 128;
    const int bn = blockIdx.x * 64;

    const int am0 = tid >> 2;               // 0..63
    const int am1 = am0 + 64;
    const int ak4 = (tid & 3) * 4;
    const int pc = (tid & 3) * 2;
    int agr0 = bm + am0; if (agr0 >= M) agr0 = M - 1;
    int agr1 = bm + am1; if (agr1 >= M) agr1 = M - 1;
    const int gn = bn + am0;
    const float* Bp = (gn < Nhalf) ? B0 : B1;
    const int bcol = (gn < Nhalf) ? gn : gn - Nhalf;

    float4 aReg0 = *(const float4*)&A[(size_t)agr0 * K + ak4];
    float4 aReg1 = *(const float4*)&A[(size_t)agr1 * K + ak4];
    float4 bReg = *(const float4*)&Bp[(size_t)bcol * K + ak4];

    // fill buffer 0
    {
        unsigned hi, lo;
        split2_bf16(aReg0.x, aReg0.y, hi, lo); AsH[0][am0][pc] = hi; AsL[0][am0][pc] = lo;
        split2_bf16(aReg0.z, aReg0.w, hi, lo); AsH[0][am0][pc + 1] = hi; AsL[0][am0][pc + 1] = lo;
        split2_bf16(aReg1.x, aReg1.y, hi, lo); AsH[0][am1][pc] = hi; AsL[0][am1][pc] = lo;
        split2_bf16(aReg1.z, aReg1.w, hi, lo); AsH[0][am1][pc + 1] = hi; AsL[0][am1][pc + 1] = lo;
        split2_bf16(bReg.x, bReg.y, hi, lo); BsH[0][am0][pc] = hi; BsL[0][am0][pc] = lo;
        split2_bf16(bReg.z, bReg.w, hi, lo); BsH[0][am0][pc + 1] = hi; BsL[0][am0][pc + 1] = lo;
    }

    float acc[2][4][4] = {};
    int buf = 0;

    for (int k0 = 0; k0 < K; k0 += 16) {
        __syncthreads();   // buf ready for all warps
        bool more = (k0 + 16) < K;
        if (more) {
            aReg0 = *(const float4*)&A[(size_t)agr0 * K + k0 + 16 + ak4];
            aReg1 = *(const float4*)&A[(size_t)agr1 * K + k0 + 16 + ak4];
            bReg = *(const float4*)&Bp[(size_t)bcol * K + k0 + 16 + ak4];
        }

        unsigned ahi[2][4], alo[2][4], bhi[4][2], blo[4][2];
#pragma unroll
        for (int mt = 0; mt < 2; mt++) {
            int r = wm * 32 + mt * 16 + groupID;
            ahi[mt][0] = AsH[buf][r][tg];         alo[mt][0] = AsL[buf][r][tg];
            ahi[mt][1] = AsH[buf][r + 8][tg];     alo[mt][1] = AsL[buf][r + 8][tg];
            ahi[mt][2] = AsH[buf][r][tg + 4];     alo[mt][2] = AsL[buf][r][tg + 4];
            ahi[mt][3] = AsH[buf][r + 8][tg + 4]; alo[mt][3] = AsL[buf][r + 8][tg + 4];
        }
#pragma unroll
        for (int nt = 0; nt < 4; nt++) {
            int n = wn * 32 + nt * 8 + groupID;
            bhi[nt][0] = BsH[buf][n][tg];     blo[nt][0] = BsL[buf][n][tg];
            bhi[nt][1] = BsH[buf][n][tg + 4]; blo[nt][1] = BsL[buf][n][tg + 4];
        }
#pragma unroll
        for (int mt = 0; mt < 2; mt++)
#pragma unroll
            for (int nt = 0; nt < 4; nt++) {
                mma_bf16(acc[mt][nt], ahi[mt], bhi[nt]);
                mma_bf16(acc[mt][nt], alo[mt], bhi[nt]);
                mma_bf16(acc[mt][nt], ahi[mt], blo[nt]);
            }

        if (more) {
            int nb = buf ^ 1;
            unsigned hi, lo;
            split2_bf16(aReg0.x, aReg0.y, hi, lo); AsH[nb][am0][pc] = hi; AsL[nb][am0][pc] = lo;
            split2_bf16(aReg0.z, aReg0.w, hi, lo); AsH[nb][am0][pc + 1] = hi; AsL[nb][am0][pc + 1] = lo;
            split2_bf16(aReg1.x, aReg1.y, hi, lo); AsH[nb][am1][pc] = hi; AsL[nb][am1][pc] = lo;
            split2_bf16(aReg1.z, aReg1.w, hi, lo); AsH[nb][am1][pc + 1] = hi; AsL[nb][am1][pc + 1] = lo;
            split2_bf16(bReg.x, bReg.y, hi, lo); BsH[nb][am0][pc] = hi; BsL[nb][am0][pc] = lo;
            split2_bf16(bReg.z, bReg.w, hi, lo); BsH[nb][am0][pc + 1] = hi; BsL[nb][am0][pc + 1] = lo;
        }
        buf ^= 1;
    }

#pragma unroll
    for (int mt = 0; mt < 2; mt++) {
        int row0 = bm + wm * 32 + mt * 16 + groupID;
#pragma unroll
        for (int nt = 0; nt < 4; nt++) {
            int col0 = bn + wn * 32 + nt * 8 + tg * 2;
            float b0 = (col0 < Nhalf) ? bias0[col0] : bias1[col0 - Nhalf];
            float b1 = (col0 + 1 < Nhalf) ? bias0[col0 + 1] : bias1[col0 + 1 - Nhalf];
            if (row0 < M) {
                C[(size_t)row0 * N + col0] = acc[mt][nt][0] + b0;
                C[(size_t)row0 * N + col0 + 1] = acc[mt][nt][1] + b1;
            }
            if (row0 + 8 < M) {
                C[(size_t)(row0 + 8) * N + col0] = acc[mt][nt][2] + b0;
                C[(size_t)(row0 + 8) * N + col0 + 1] = acc[mt][nt][3] + b1;
            }
        }
    }
}

// ---------------- CSR edge pass, layer 1 (C=256): warp per (dst, head), pipelined ----------------
__global__ __launch_bounds__(256) void gat_edge1_k(
    const int* __restrict__ srcs, const float* __restrict__ eas,
    const int* __restrict__ off,
    const float* __restrict__ xlr, const float* __restrict__ We,
    const float* __restrict__ att, float* __restrict__ outv) {
    int gw = (blockIdx.x * 256 + threadIdx.x) >> 5;
    int lane = threadIdx.x & 31;
    if (gw >= NN * H) return;
    int h = gw & 1;
    int d = gw >> 1;
    const int STR = 2 * D1;
    const int c0 = lane * 4, c1 = 128 + lane * 4;

    const float* xrd = xlr + (size_t)d * STR + D1 + h * C1;
    float4 xr_a = *(const float4*)&xrd[c0];
    float4 xr_b = *(const float4*)&xrd[c1];
    const float* Weh = We + h * C1;
    float4 w_a = *(const float4*)&Weh[c0];
    float4 w_b = *(const float4*)&Weh[c1];
    const float* ath = att + h * C1;
    float4 t_a = *(const float4*)&ath[c0];
    float4 t_b = *(const float4*)&ath[c1];

    float4 acc_a = {0, 0, 0, 0}, acc_b = {0, 0, 0, 0};
    float denom = 0.f;
    int i0 = off[d], i1 = off[d + 1];
    int degn = i1 - i0;

    // preload first iteration
    float easum, eac;
    int sc;
    if (degn > 0) {
        sc = srcs[i0];
        eac = eas[i0];
        easum = eac;
    } else {
        sc = d;
        eac = 0.f;
        easum = 0.f;
    }
    const float* xp = xlr + (size_t)sc * STR + h * C1;
    float4 a_a = *(const float4*)&xp[c0];
    float4 a_b = *(const float4*)&xp[c1];

    for (int i = i0; i <= i1; i++) {
        float4 n_a, n_b;
        float ean = 0.f;
        if (i < i1) {
            int sn;
            if (i + 1 < i1) {
                sn = srcs[i + 1];
                ean = eas[i + 1];
                easum += ean;
            } else {
                sn = d;
                ean = easum / (float)degn;
            }
            const float* np = xlr + (size_t)sn * STR + h * C1;
            n_a = *(const float4*)&np[c0];
            n_b = *(const float4*)&np[c1];
        }
        float v, lg = 0.f;
        v = a_a.x + xr_a.x + eac * w_a.x; v = v > 0.f ? v : NEG * v; lg += v * t_a.x;
        v = a_a.y + xr_a.y + eac * w_a.y; v = v > 0.f ? v : NEG * v; lg += v * t_a.y;
        v = a_a.z + xr_a.z + eac * w_a.z; v = v > 0.f ? v : NEG * v; lg += v * t_a.z;
        v = a_a.w + xr_a.w + eac * w_a.w; v = v > 0.f ? v : NEG * v; lg += v * t_a.w;
        v = a_b.x + xr_b.x + eac * w_b.x; v = v > 0.f ? v : NEG * v; lg += v * t_b.x;
        v = a_b.y + xr_b.y + eac * w_b.y; v = v > 0.f ? v : NEG * v; lg += v * t_b.y;
        v = a_b.z + xr_b.z + eac * w_b.z; v = v > 0.f ? v : NEG * v; lg += v * t_b.z;
        v = a_b.w + xr_b.w + eac * w_b.w; v = v > 0.f ? v : NEG * v; lg += v * t_b.w;
#pragma unroll
        for (int o = 16; o > 0; o >>= 1) lg += __shfl_xor_sync(0xffffffffu, lg, o);
        float p = __expf(lg);
        denom += p;
        acc_a.x += p * a_a.x; acc_a.y += p * a_a.y; acc_a.z += p * a_a.z; acc_a.w += p * a_a.w;
        acc_b.x += p * a_b.x; acc_b.y += p * a_b.y; acc_b.z += p * a_b.z; acc_b.w += p * a_b.w;
        if (i < i1) {
            a_a = n_a;
            a_b = n_b;
            eac = ean;
        }
    }
    float inv = 1.f / denom;
    float* od = outv + (size_t)d * D1 + h * C1;
    float4 o_a = {acc_a.x * inv, acc_a.y * inv, acc_a.z * inv, acc_a.w * inv};
    float4 o_b = {acc_b.x * inv, acc_b.y * inv, acc_b.z * inv, acc_b.w * inv};
    *(float4*)&od[c0] = o_a;
    *(float4*)&od[c1] = o_b;
}

// ---------------- CSR edge pass, layer 2 (C=64): warp per dst, pipelined ----------------
__global__ __launch_bounds__(256) void gat_edge2_k(
    const int* __restrict__ srcs, const float* __restrict__ eas,
    const int* __restrict__ off,
    const float* __restrict__ xlr, const float* __restrict__ We,
    const float* __restrict__ att, float* __restrict__ outv) {
    int gw = (blockIdx.x * 256 + threadIdx.x) >> 5;
    int lane = threadIdx.x & 31;
    if (gw >= NN) return;
    int d = gw;
    const int STR = 2 * D2;
    int h = lane >> 4;
    int cl = (lane & 15) * 4;
    int gc = h * C2 + cl;

    const float* xrd = xlr + (size_t)d * STR + D2;
    float4 xr_v = *(const float4*)&xrd[gc];
    float4 w_v = *(const float4*)&We[gc];
    float4 t_v = *(const float4*)&att[gc];

    float4 acc = {0, 0, 0, 0};
    float denom = 0.f;
    int i0 = off[d], i1 = off[d + 1];
    int degn = i1 - i0;

    float easum, eac;
    int sc;
    if (degn > 0) {
        sc = srcs[i0];
        eac = eas[i0];
        easum = eac;
    } else {
        sc = d;
        eac = 0.f;
        easum = 0.f;
    }
    float4 a = *(const float4*)&xlr[(size_t)sc * STR + gc];

    for (int i = i0; i <= i1; i++) {
        float4 n;
        float ean = 0.f;
        if (i < i1) {
            int sn;
            if (i + 1 < i1) {
                sn = srcs[i + 1];
                ean = eas[i + 1];
                easum += ean;
            } else {
                sn = d;
                ean = easum / (float)degn;
            }
            n = *(const float4*)&xlr[(size_t)sn * STR + gc];
        }
        float v, lg = 0.f;
        v = a.x + xr_v.x + eac * w_v.x; v = v > 0.f ? v : NEG * v; lg += v * t_v.x;
        v = a.y + xr_v.y + eac * w_v.y; v = v > 0.f ? v : NEG * v; lg += v * t_v.y;
        v = a.z + xr_v.z + eac * w_v.z; v = v > 0.f ? v : NEG * v; lg += v * t_v.z;
        v = a.w + xr_v.w + eac * w_v.w; v = v > 0.f ? v : NEG * v; lg += v * t_v.w;
#pragma unroll
        for (int o = 8; o > 0; o >>= 1) lg += __shfl_xor_sync(0xffffffffu, lg, o);
        float p = __expf(lg);
        denom += p;
        acc.x += p * a.x; acc.y += p * a.y; acc.z += p * a.z; acc.w += p * a.w;
        if (i < i1) {
            a = n;
            eac = ean;
        }
    }
    float inv = 1.f / denom;
    float* od = outv + (size_t)d * D2 + gc;
    float4 o = {acc.x * inv, acc.y * inv, acc.z * inv, acc.w * inv};
    *(float4*)&od[0] = o;
}

// ---------------- bias + (silu) + rmsnorm ----------------
__global__ void postact_rms_k(const float* __restrict__ acc, const float* __restrict__ bias,
                              const float* __restrict__ w, float* __restrict__ out,
                              int D, int do_silu) {
    int n = blockIdx.x;
    float vals[2];
    float ss = 0.f;
    int nv = 0;
    for (int j = threadIdx.x; j < D; j += blockDim.x) {
        float v = acc[(size_t)n * D + j] + bias[j];
        if (do_silu) v = v / (1.f + __expf(-v));
        vals[nv++] = v;
        ss += v * v;
    }
    __shared__ float red[32];
    int lane = threadIdx.x & 31, wid = threadIdx.x >> 5;
#pragma unroll
    for (int o = 16; o > 0; o >>= 1) ss += __shfl_down_sync(0xffffffffu, ss, o);
    if (lane == 0) red[wid] = ss;
    __syncthreads();
    if (wid == 0) {
        float s2 = (lane < (blockDim.x >> 5)) ? red[lane] : 0.f;
#pragma unroll
        for (int o = 16; o > 0; o >>= 1) s2 += __shfl_down_sync(0xffffffffu, s2, o);
        if (lane == 0) red[0] = s2;
    }
    __syncthreads();
    float inv = rsqrtf(red[0] / (float)D + EPS);
    nv = 0;
    for (int j = threadIdx.x; j < D; j += blockDim.x)
        out[(size_t)n * D + j] = vals[nv++] * inv * w[j];
}

// ---------------- classifier ----------------
__global__ void out_gemm_k(const float* __restrict__ h, const float* __restrict__ W,
                           float* __restrict__ out, int N, int K, int Cn) {
    extern __shared__ float Ws[];
    for (int i = threadIdx.x; i < Cn * K; i += blockDim.x) Ws[i] = W[i];
    __syncthreads();
    int idx = blockIdx.x * blockDim.x + threadIdx.x;
    if (idx >= N * Cn) return;
    int n = idx / Cn, c = idx % Cn;
    const float* hr = h + (size_t)n * K;
    const float* wr = Ws + c * K;
    float s = 0.f;
#pragma unroll 8
    for (int k = 0; k < K; k++) s += hr[k] * wr[k];
    out[idx] = s;
}

// ---------------- launch ----------------
static void* sym(const void* s) {
    void* p = nullptr;
    cudaGetSymbolAddress(&p, s);
    return p;
}

extern "C" void kernel_launch(void* const* d_in, const int* in_sizes, int n_in,
                              void* d_out, int out_size) {
    const float* x     = (const float*)d_in[0];
    const int*   ei    = (const int*)d_in[1];
    const float* eattr = (const float*)d_in[2];
    const float* Wl1   = (const float*)d_in[3];
    const float* bl1   = (const float*)d_in[4];
    const float* Wr1   = (const float*)d_in[5];
    const float* br1   = (const float*)d_in[6];
    const float* We1   = (const float*)d_in[7];
    const float* att1  = (const float*)d_in[8];
    const float* bias1 = (const float*)d_in[9];
    const float* Wl2   = (const float*)d_in[10];
    const float* bl2   = (const float*)d_in[11];
    const float* Wr2   = (const float*)d_in[12];
    const float* br2   = (const float*)d_in[13];
    const float* We2   = (const float*)d_in[14];
    const float* att2  = (const float*)d_in[15];
    const float* bias2 = (const float*)d_in[16];
    const float* w_ln1 = (const float*)d_in[17];
    const float* w_ln3 = (const float*)d_in[18];
    const float* W_out = (const float*)d_in[19];
    float* out = (float*)d_out;

    const int* srcp = ei;
    const int* dstp = ei + NE;

    float* xlr1 = (float*)sym(g_xlr1);
    float* acc1 = (float*)sym(g_acc1);
    float* xlr2 = (float*)sym(g_xlr2);
    float* acc2 = (float*)sym(g_acc2);
    int* deg    = (int*)sym(g_deg);
    int* off    = (int*)sym(g_off);
    int* cursor = (int*)sym(g_cursor);
    int* srcs   = (int*)sym(g_srcs);
    float* eas  = (float*)sym(g_eas);

    // 0-2: CSR histogram + scan
    zero_deg_k<<<(NN + 255) / 256, 256>>>(deg);
    hist_k<<<(NE + 255) / 256, 256>>>(dstp, deg);
    scan_k<<<1, 1024>>>(deg, off, cursor);

    // 3: layer 1 fused transforms (profiler capture slot): N=1024 -> 16 col tiles
    dim3 g1(2 * D1 / 64, (NN + 127) / 128);
    gemm_bf3_k<<<g1, 256>>>(x, Wl1, Wr1, bl1, br1, xlr1, NN, D1, D2);

    // 4: permute edges into CSR order
    scatter_k<<<(NE + 255) / 256, 256>>>(srcp, dstp, eattr, cursor, srcs, eas);

    // 5: CSR edge pass layer 1
    gat_edge1_k<<<(NN * H * 32 + 255) / 256, 256>>>(srcs, eas, off, xlr1, We1, att1, acc1);

    // 6: silu + rmsnorm
    postact_rms_k<<<NN, 256>>>(acc1, bias1, w_ln1, acc1, D1, 1);

    // 7: layer 2 fused transforms
    dim3 g2(2 * D2 / 64, (NN + 127) / 128);
    gemm_bf3_k<<<g2, 256>>>(acc1, Wl2, Wr2, bl2, br2, xlr2, NN, D2, D1);

    // 8: CSR edge pass layer 2
    gat_edge2_k<<<(NN * 32 + 255) / 256, 256>>>(srcs, eas, off, xlr2, We2, att2, acc2);

    // 9: rmsnorm
    postact_rms_k<<<NN, 256>>>(acc2, bias2, w_ln3, acc2, D2, 0);

    // 10: classifier
    int ntot = NN * NCLS;
    out_gemm_k<<<(ntot + 255) / 256, 256, NCLS * D2 * sizeof(float)>>>(acc2, W_out, out, NN, D2, NCLS);
}

// round 9
// speedup vs baseline: 1.1361x; 1.1291x over previous
#include <cuda_runtime.h>
#include <cuda_fp16.h>
#include <cuda_bf16.h>

#define NN 30000
#define NE 240000
#define D1 512
#define D2 128
#define H 2
#define C1 256
#define C2 64
#define NCLS 20
#define EPS 1e-5f
#define NEG 0.2f

// ---------------- scratch ----------------
__device__ half g_xlh1[(size_t)NN * D1];   // xl layer1, fp16 (gathered)
__device__ float g_xr1[(size_t)NN * D1];   // xr layer1, fp32 (read once per dst)
__device__ half g_xlh2[(size_t)NN * D2];
__device__ float g_xr2[(size_t)NN * D2];
__device__ float g_acc1[(size_t)NN * D1];
__device__ float g_acc2[(size_t)NN * D2];
__device__ int g_deg[NN];
__device__ int g_off[NN + 1];
__device__ int g_cursor[NN];
__device__ int g_srcs[NE];
__device__ float g_eas[NE];

// ---------------- CSR build ----------------
__global__ void zero_deg_k(int* deg) {
    int i = blockIdx.x * blockDim.x + threadIdx.x;
    if (i < NN) deg[i] = 0;
}
__global__ void hist_k(const int* __restrict__ dst, int* __restrict__ deg) {
    int e = blockIdx.x * blockDim.x + threadIdx.x;
    if (e < NE) atomicAdd(&deg[dst[e]], 1);
}
__global__ __launch_bounds__(1024) void scan_k(const int* __restrict__ deg,
                                               int* __restrict__ off, int* __restrict__ cursor) {
    __shared__ int partial[1024];
    int t = threadIdx.x;
    const int CH = (NN + 1023) / 1024;
    int base = t * CH;
    int s = 0;
    for (int i = 0; i < CH; i++) {
        int idx = base + i;
        if (idx < NN) s += deg[idx];
    }
    partial[t] = s;
    __syncthreads();
    for (int o = 1; o < 1024; o <<= 1) {
        int v = (t >= o) ? partial[t - o] : 0;
        __syncthreads();
        partial[t] += v;
        __syncthreads();
    }
    int run = (t == 0) ? 0 : partial[t - 1];
    for (int i = 0; i < CH; i++) {
        int idx = base + i;
        if (idx < NN) {
            off[idx] = run;
            cursor[idx] = run;
            run += deg[idx];
        }
    }
    if (t == 1023) off[NN] = partial[1023];
}
__global__ void scatter_k(const int* __restrict__ src, const int* __restrict__ dst,
                          const float* __restrict__ eattr, int* __restrict__ cursor,
                          int* __restrict__ srcs, float* __restrict__ eas) {
    int e = blockIdx.x * blockDim.x + threadIdx.x;
    if (e < NE) {
        int pos = atomicAdd(&cursor[dst[e]], 1);
        srcs[pos] = src[e];
        eas[pos] = eattr[e];
    }
}

// ---------------- fp16 MMA ----------------
__device__ __forceinline__ void mma_f16(float* c, const unsigned* a, const unsigned* b) {
    asm volatile(
        "mma.sync.aligned.m16n8k16.row.col.f32.f16.f16.f32 "
        "{%0,%1,%2,%3}, {%4,%5,%6,%7}, {%8,%9}, {%0,%1,%2,%3};\n"
        : "+f"(c[0]), "+f"(c[1]), "+f"(c[2]), "+f"(c[3])
        : "r"(a[0]), "r"(a[1]), "r"(a[2]), "r"(a[3]), "r"(b[0]), "r"(b[1]));
}
__device__ __forceinline__ unsigned pack_h2(float f0, float f1) {
    __half2 h = __floats2half2_rn(f0, f1);
    return *(unsigned*)&h;
}

// ---------------- dual-B fp16 TC GEMM, 128x64 block, 32x32 warp tile, double buffer ----------------
// xl half (cols [0,Nhalf)) -> Cl ; xr fp32 (cols [Nhalf,2Nhalf)) -> Cr
__global__ __launch_bounds__(256) void gemm_f16_k(
    const float* __restrict__ A,
    const float* __restrict__ B0, const float* __restrict__ B1,
    const float* __restrict__ bias0, const float* __restrict__ bias1,
    half* __restrict__ Cl, float* __restrict__ Cr, int M, int Nhalf, int K) {
    __shared__ unsigned As[2][128][12];
    __shared__ unsigned Bs[2][64][12];

    const int tid = threadIdx.x;
    const int lane = tid & 31;
    const int warp = tid >> 5;
    const int wm = warp >> 1;
    const int wn = warp & 1;
    const int groupID = lane >> 2;
    const int tg = lane & 3;

    const int bm = blockIdx.y * 128;
    const int bn = blockIdx.x * 64;

    const int am0 = tid >> 2;
    const int am1 = am0 + 64;
    const int ak4 = (tid & 3) * 4;
    const int pc = (tid & 3) * 2;
    int agr0 = bm + am0; if (agr0 >= M) agr0 = M - 1;
    int agr1 = bm + am1; if (agr1 >= M) agr1 = M - 1;
    const int gn = bn + am0;
    const float* Bp = (gn < Nhalf) ? B0 : B1;
    const int bcol = (gn < Nhalf) ? gn : gn - Nhalf;

    float4 aReg0 = *(const float4*)&A[(size_t)agr0 * K + ak4];
    float4 aReg1 = *(const float4*)&A[(size_t)agr1 * K + ak4];
    float4 bReg = *(const float4*)&Bp[(size_t)bcol * K + ak4];

    As[0][am0][pc] = pack_h2(aReg0.x, aReg0.y);
    As[0][am0][pc + 1] = pack_h2(aReg0.z, aReg0.w);
    As[0][am1][pc] = pack_h2(aReg1.x, aReg1.y);
    As[0][am1][pc + 1] = pack_h2(aReg1.z, aReg1.w);
    Bs[0][am0][pc] = pack_h2(bReg.x, bReg.y);
    Bs[0][am0][pc + 1] = pack_h2(bReg.z, bReg.w);

    float acc[2][4][4] = {};
    int buf = 0;

    for (int k0 = 0; k0 < K; k0 += 16) {
        __syncthreads();
        bool more = (k0 + 16) < K;
        if (more) {
            aReg0 = *(const float4*)&A[(size_t)agr0 * K + k0 + 16 + ak4];
            aReg1 = *(const float4*)&A[(size_t)agr1 * K + k0 + 16 + ak4];
            bReg = *(const float4*)&Bp[(size_t)bcol * K + k0 + 16 + ak4];
        }

        unsigned ah[2][4], bh[4][2];
#pragma unroll
        for (int mt = 0; mt < 2; mt++) {
            int r = wm * 32 + mt * 16 + groupID;
            ah[mt][0] = As[buf][r][tg];
            ah[mt][1] = As[buf][r + 8][tg];
            ah[mt][2] = As[buf][r][tg + 4];
            ah[mt][3] = As[buf][r + 8][tg + 4];
        }
#pragma unroll
        for (int nt = 0; nt < 4; nt++) {
            int n = wn * 32 + nt * 8 + groupID;
            bh[nt][0] = Bs[buf][n][tg];
            bh[nt][1] = Bs[buf][n][tg + 4];
        }
#pragma unroll
        for (int mt = 0; mt < 2; mt++)
#pragma unroll
            for (int nt = 0; nt < 4; nt++)
                mma_f16(acc[mt][nt], ah[mt], bh[nt]);

        if (more) {
            int nb = buf ^ 1;
            As[nb][am0][pc] = pack_h2(aReg0.x, aReg0.y);
            As[nb][am0][pc + 1] = pack_h2(aReg0.z, aReg0.w);
            As[nb][am1][pc] = pack_h2(aReg1.x, aReg1.y);
            As[nb][am1][pc + 1] = pack_h2(aReg1.z, aReg1.w);
            Bs[nb][am0][pc] = pack_h2(bReg.x, bReg.y);
            Bs[nb][am0][pc + 1] = pack_h2(bReg.z, bReg.w);
        }
        buf ^= 1;
    }

#pragma unroll
    for (int mt = 0; mt < 2; mt++) {
        int row0 = bm + wm * 32 + mt * 16 + groupID;
#pragma unroll
        for (int nt = 0; nt < 4; nt++) {
            int col0 = bn + wn * 32 + nt * 8 + tg * 2;
            if (col0 < Nhalf) {
                float b0 = bias0[col0], b1 = bias0[col0 + 1];
                if (row0 < M)
                    *(__half2*)&Cl[(size_t)row0 * Nhalf + col0] =
                        __floats2half2_rn(acc[mt][nt][0] + b0, acc[mt][nt][1] + b1);
                if (row0 + 8 < M)
                    *(__half2*)&Cl[(size_t)(row0 + 8) * Nhalf + col0] =
                        __floats2half2_rn(acc[mt][nt][2] + b0, acc[mt][nt][3] + b1);
            } else {
                int cc = col0 - Nhalf;
                float b0 = bias1[cc], b1 = bias1[cc + 1];
                if (row0 < M) {
                    Cr[(size_t)row0 * Nhalf + cc] = acc[mt][nt][0] + b0;
                    Cr[(size_t)row0 * Nhalf + cc + 1] = acc[mt][nt][1] + b1;
                }
                if (row0 + 8 < M) {
                    Cr[(size_t)(row0 + 8) * Nhalf + cc] = acc[mt][nt][2] + b0;
                    Cr[(size_t)(row0 + 8) * Nhalf + cc + 1] = acc[mt][nt][3] + b1;
                }
            }
        }
    }
}

// ---------------- CSR edge pass, layer 1 (C=256): warp per (dst, head), fp16 gather ----------------
__global__ __launch_bounds__(256) void gat_edge1_k(
    const int* __restrict__ srcs, const float* __restrict__ eas,
    const int* __restrict__ off,
    const half* __restrict__ xlh, const float* __restrict__ xr,
    const float* __restrict__ We, const float* __restrict__ att,
    float* __restrict__ outv) {
    int gw = (blockIdx.x * 256 + threadIdx.x) >> 5;
    int lane = threadIdx.x & 31;
    if (gw >= NN * H) return;
    int h = gw & 1;
    int d = gw >> 1;
    const int cb = h * C1 + lane * 8;   // 8 contiguous cols per lane

    const float* xrd = xr + (size_t)d * D1 + cb;
    float4 xr_a = *(const float4*)&xrd[0];
    float4 xr_b = *(const float4*)&xrd[4];
    float4 w_a = *(const float4*)&We[cb];
    float4 w_b = *(const float4*)&We[cb + 4];
    float4 t_a = *(const float4*)&att[cb];
    float4 t_b = *(const float4*)&att[cb + 4];

    float4 acc_a = {0, 0, 0, 0}, acc_b = {0, 0, 0, 0};
    float denom = 0.f;
    int i0 = off[d], i1 = off[d + 1];
    int degn = i1 - i0;

    float easum, eac;
    int sc;
    if (degn > 0) {
        sc = srcs[i0];
        eac = eas[i0];
        easum = eac;
    } else {
        sc = d;
        eac = 0.f;
        easum = 0.f;
    }
    uint4 raw = *(const uint4*)&xlh[(size_t)sc * D1 + cb];

    for (int i = i0; i <= i1; i++) {
        uint4 nraw;
        float ean = 0.f;
        if (i < i1) {
            int sn;
            if (i + 1 < i1) {
                sn = srcs[i + 1];
                ean = eas[i + 1];
                easum += ean;
            } else {
                sn = d;
                ean = easum / (float)degn;
            }
            nraw = *(const uint4*)&xlh[(size_t)sn * D1 + cb];
        }
        const __half2* hp = (const __half2*)&raw;
        float2 f0 = __half22float2(hp[0]);
        float2 f1 = __half22float2(hp[1]);
        float2 f2 = __half22float2(hp[2]);
        float2 f3 = __half22float2(hp[3]);
        float v, lg = 0.f;
        v = f0.x + xr_a.x + eac * w_a.x; v = v > 0.f ? v : NEG * v; lg += v * t_a.x;
        v = f0.y + xr_a.y + eac * w_a.y; v = v > 0.f ? v : NEG * v; lg += v * t_a.y;
        v = f1.x + xr_a.z + eac * w_a.z; v = v > 0.f ? v : NEG * v; lg += v * t_a.z;
        v = f1.y + xr_a.w + eac * w_a.w; v = v > 0.f ? v : NEG * v; lg += v * t_a.w;
        v = f2.x + xr_b.x + eac * w_b.x; v = v > 0.f ? v : NEG * v; lg += v * t_b.x;
        v = f2.y + xr_b.y + eac * w_b.y; v = v > 0.f ? v : NEG * v; lg += v * t_b.y;
        v = f3.x + xr_b.z + eac * w_b.z; v = v > 0.f ? v : NEG * v; lg += v * t_b.z;
        v = f3.y + xr_b.w + eac * w_b.w; v = v > 0.f ? v : NEG * v; lg += v * t_b.w;
#pragma unroll
        for (int o = 16; o > 0; o >>= 1) lg += __shfl_xor_sync(0xffffffffu, lg, o);
        float p = __expf(lg);
        denom += p;
        acc_a.x += p * f0.x; acc_a.y += p * f0.y; acc_a.z += p * f1.x; acc_a.w += p * f1.y;
        acc_b.x += p * f2.x; acc_b.y += p * f2.y; acc_b.z += p * f3.x; acc_b.w += p * f3.y;
        if (i < i1) {
            raw = nraw;
            eac = ean;
        }
    }
    float inv = 1.f / denom;
    float* od = outv + (size_t)d * D1 + cb;
    float4 o_a = {acc_a.x * inv, acc_a.y * inv, acc_a.z * inv, acc_a.w * inv};
    float4 o_b = {acc_b.x * inv, acc_b.y * inv, acc_b.z * inv, acc_b.w * inv};
    *(float4*)&od[0] = o_a;
    *(float4*)&od[4] = o_b;
}

// ---------------- CSR edge pass, layer 2 (C=64): warp per dst, fp16 gather ----------------
__global__ __launch_bounds__(256) void gat_edge2_k(
    const int* __restrict__ srcs, const float* __restrict__ eas,
    const int* __restrict__ off,
    const half* __restrict__ xlh, const float* __restrict__ xr,
    const float* __restrict__ We, const float* __restrict__ att,
    float* __restrict__ outv) {
    int gw = (blockIdx.x * 256 + threadIdx.x) >> 5;
    int lane = threadIdx.x & 31;
    if (gw >= NN) return;
    int d = gw;
    int h = lane >> 4;
    int cl = (lane & 15) * 4;
    int gc = h * C2 + cl;

    float4 xr_v = *(const float4*)&xr[(size_t)d * D2 + gc];
    float4 w_v = *(const float4*)&We[gc];
    float4 t_v = *(const float4*)&att[gc];

    float4 acc = {0, 0, 0, 0};
    float denom = 0.f;
    int i0 = off[d], i1 = off[d + 1];
    int degn = i1 - i0;

    float easum, eac;
    int sc;
    if (degn > 0) {
        sc = srcs[i0];
        eac = eas[i0];
        easum = eac;
    } else {
        sc = d;
        eac = 0.f;
        easum = 0.f;
    }
    uint2 raw = *(const uint2*)&xlh[(size_t)sc * D2 + gc];

    for (int i = i0; i <= i1; i++) {
        uint2 nraw;
        float ean = 0.f;
        if (i < i1) {
            int sn;
            if (i + 1 < i1) {
                sn = srcs[i + 1];
                ean = eas[i + 1];
                easum += ean;
            } else {
                sn = d;
                ean = easum / (float)degn;
            }
            nraw = *(const uint2*)&xlh[(size_t)sn * D2 + gc];
        }
        const __half2* hp = (const __half2*)&raw;
        float2 f0 = __half22float2(hp[0]);
        float2 f1 = __half22float2(hp[1]);
        float v, lg = 0.f;
        v = f0.x + xr_v.x + eac * w_v.x; v = v > 0.f ? v : NEG * v; lg += v * t_v.x;
        v = f0.y + xr_v.y + eac * w_v.y; v = v > 0.f ? v : NEG * v; lg += v * t_v.y;
        v = f1.x + xr_v.z + eac * w_v.z; v = v > 0.f ? v : NEG * v; lg += v * t_v.z;
        v = f1.y + xr_v.w + eac * w_v.w; v = v > 0.f ? v : NEG * v; lg += v * t_v.w;
#pragma unroll
        for (int o = 8; o > 0; o >>= 1) lg += __shfl_xor_sync(0xffffffffu, lg, o);
        float p = __expf(lg);
        denom += p;
        acc.x += p * f0.x; acc.y += p * f0.y; acc.z += p * f1.x; acc.w += p * f1.y;
        if (i < i1) {
            raw = nraw;
            eac = ean;
        }
    }
    float inv = 1.f / denom;
    float* od = outv + (size_t)d * D2 + gc;
    float4 o = {acc.x * inv, acc.y * inv, acc.z * inv, acc.w * inv};
    *(float4*)&od[0] = o;
}

// ---------------- bias + (silu) + rmsnorm ----------------
__global__ void postact_rms_k(const float* __restrict__ acc, const float* __restrict__ bias,
                              const float* __restrict__ w, float* __restrict__ out,
                              int D, int do_silu) {
    int n = blockIdx.x;
    float vals[2];
    float ss = 0.f;
    int nv = 0;
    for (int j = threadIdx.x; j < D; j += blockDim.x) {
        float v = acc[(size_t)n * D + j] + bias[j];
        if (do_silu) v = v / (1.f + __expf(-v));
        vals[nv++] = v;
        ss += v * v;
    }
    __shared__ float red[32];
    int lane = threadIdx.x & 31, wid = threadIdx.x >> 5;
#pragma unroll
    for (int o = 16; o > 0; o >>= 1) ss += __shfl_down_sync(0xffffffffu, ss, o);
    if (lane == 0) red[wid] = ss;
    __syncthreads();
    if (wid == 0) {
        float s2 = (lane < (blockDim.x >> 5)) ? red[lane] : 0.f;
#pragma unroll
        for (int o = 16; o > 0; o >>= 1) s2 += __shfl_down_sync(0xffffffffu, s2, o);
        if (lane == 0) red[0] = s2;
    }
    __syncthreads();
    float inv = rsqrtf(red[0] / (float)D + EPS);
    nv = 0;
    for (int j = threadIdx.x; j < D; j += blockDim.x)
        out[(size_t)n * D + j] = vals[nv++] * inv * w[j];
}

// ---------------- classifier ----------------
__global__ void out_gemm_k(const float* __restrict__ h, const float* __restrict__ W,
                           float* __restrict__ out, int N, int K, int Cn) {
    extern __shared__ float Ws[];
    for (int i = threadIdx.x; i < Cn * K; i += blockDim.x) Ws[i] = W[i];
    __syncthreads();
    int idx = blockIdx.x * blockDim.x + threadIdx.x;
    if (idx >= N * Cn) return;
    int n = idx / Cn, c = idx % Cn;
    const float* hr = h + (size_t)n * K;
    const float* wr = Ws + c * K;
    float s = 0.f;
#pragma unroll 8
    for (int k = 0; k < K; k++) s += hr[k] * wr[k];
    out[idx] = s;
}

// ---------------- launch ----------------
static void* sym(const void* s) {
    void* p = nullptr;
    cudaGetSymbolAddress(&p, s);
    return p;
}

extern "C" void kernel_launch(void* const* d_in, const int* in_sizes, int n_in,
                              void* d_out, int out_size) {
    const float* x     = (const float*)d_in[0];
    const int*   ei    = (const int*)d_in[1];
    const float* eattr = (const float*)d_in[2];
    const float* Wl1   = (const float*)d_in[3];
    const float* bl1   = (const float*)d_in[4];
    const float* Wr1   = (const float*)d_in[5];
    const float* br1   = (const float*)d_in[6];
    const float* We1   = (const float*)d_in[7];
    const float* att1  = (const float*)d_in[8];
    const float* bias1 = (const float*)d_in[9];
    const float* Wl2   = (const float*)d_in[10];
    const float* bl2   = (const float*)d_in[11];
    const float* Wr2   = (const float*)d_in[12];
    const float* br2   = (const float*)d_in[13];
    const float* We2   = (const float*)d_in[14];
    const float* att2  = (const float*)d_in[15];
    const float* bias2 = (const float*)d_in[16];
    const float* w_ln1 = (const float*)d_in[17];
    const float* w_ln3 = (const float*)d_in[18];
    const float* W_out = (const float*)d_in[19];
    float* out = (float*)d_out;

    const int* srcp = ei;
    const int* dstp = ei + NE;

    half* xlh1  = (half*)sym(g_xlh1);
    float* xr1  = (float*)sym(g_xr1);
    half* xlh2  = (half*)sym(g_xlh2);
    float* xr2  = (float*)sym(g_xr2);
    float* acc1 = (float*)sym(g_acc1);
    float* acc2 = (float*)sym(g_acc2);
    int* deg    = (int*)sym(g_deg);
    int* off    = (int*)sym(g_off);
    int* cursor = (int*)sym(g_cursor);
    int* srcs   = (int*)sym(g_srcs);
    float* eas  = (float*)sym(g_eas);

    // 0-2: CSR histogram + scan
    zero_deg_k<<<(NN + 255) / 256, 256>>>(deg);
    hist_k<<<(NE + 255) / 256, 256>>>(dstp, deg);
    scan_k<<<1, 1024>>>(deg, off, cursor);

    // 3: layer 1 fused transforms (profiler capture slot)
    dim3 g1(2 * D1 / 64, (NN + 127) / 128);
    gemm_f16_k<<<g1, 256>>>(x, Wl1, Wr1, bl1, br1, xlh1, xr1, NN, D1, D2);

    // 4: permute edges into CSR order
    scatter_k<<<(NE + 255) / 256, 256>>>(srcp, dstp, eattr, cursor, srcs, eas);

    // 5: CSR edge pass layer 1
    gat_edge1_k<<<(NN * H * 32 + 255) / 256, 256>>>(srcs, eas, off, xlh1, xr1, We1, att1, acc1);

    // 6: silu + rmsnorm
    postact_rms_k<<<NN, 256>>>(acc1, bias1, w_ln1, acc1, D1, 1);

    // 7: layer 2 fused transforms
    dim3 g2(2 * D2 / 64, (NN + 127) / 128);
    gemm_f16_k<<<g2, 256>>>(acc1, Wl2, Wr2, bl2, br2, xlh2, xr2, NN, D2, D1);

    // 8: CSR edge pass layer 2
    gat_edge2_k<<<(NN * 32 + 255) / 256, 256>>>(srcs, eas, off, xlh2, xr2, We2, att2, acc2);

    // 9: rmsnorm
    postact_rms_k<<<NN, 256>>>(acc2, bias2, w_ln3, acc2, D2, 0);

    // 10: classifier
    int ntot = NN * NCLS;
    out_gemm_k<<<(ntot + 255) / 256, 256, NCLS * D2 * sizeof(float)>>>(acc2, W_out, out, NN, D2, NCLS);
}